// round 13
// baseline (speedup 1.0000x reference)
#include <cuda_runtime.h>
#include <math.h>

#define NN 16384
#define C 64
#define KNN 40
#define CAP 192        // collection capacity per query
#define QPW 4          // queries per warp in kNN
#define PART 512       // partial-reduction blocks for BN stats
#define NB 1024        // sort buckets
#define WIN 2112       // tau window (66 chunks of 32)
#define NCH (NN / 32)  // 512 candidate chunks
#define NSC (NCH / 8)  // 64 superchunks

// ---------------- scratch (device globals; no allocation allowed) ----------
__device__ float    g_h[NN * C];     // propagated features
__device__ float4   g_s4[NN];        // learned coords (x,y,z,|s|^2), original order
__device__ float4   g_ss[NN];        // sorted by .x
__device__ int      g_perm[NN];      // sorted pos -> original idx
__device__ int      g_hist[NB];
__device__ int      g_base[NB];
__device__ int      g_cursor[NB];
__device__ unsigned g_mm[2];         // encoded min/max of coord x
__device__ float2   g_cb[NCH];       // per-chunk x min/max
__device__ float2   g_scb[NSC];      // per-superchunk x min/max
__device__ int      g_idx[NN * KNN];
__device__ float    g_ew[NN * KNN];
__device__ float    g_t[NN * C];
__device__ float    g_v[NN * C];
__device__ float    g_part[2][2][C * PART];
__device__ float    g_bn[4 * C];

__device__ __forceinline__ unsigned fenc(float f) {
    unsigned b = __float_as_uint(f);
    return b ^ ((-(int)(b >> 31)) | 0x80000000u);
}
__device__ __forceinline__ float fdec(unsigned e) {
    unsigned m = (e & 0x80000000u) ? 0x80000000u : 0xFFFFFFFFu;
    return __uint_as_float(e ^ m);
}

// ---------------- K0: reset sort scratch -----------------------------------
__global__ void k0_init() {
    int t = threadIdx.x;             // 1024 threads, 1 block
    g_hist[t] = 0;
    g_cursor[t] = 0;
    if (t == 0) { g_mm[0] = 0xFFFFFFFFu; g_mm[1] = 0u; }
}

// ---------------- K1: h = x@w_h + b_h ; s = x@w_s ; pack s4 + minmax -------
__global__ void k1_gemm_hs(const float* __restrict__ x,
                           const float* __restrict__ w_h,
                           const float* __restrict__ b_h,
                           const float* __restrict__ w_s) {
    const int ROWS = 8;
    __shared__ float sx[ROWS][C];
    __shared__ float ss[ROWS][3];
    int base = blockIdx.x * ROWS;
    int c = threadIdx.x; // 64 threads

    #pragma unroll
    for (int r = 0; r < ROWS; r++) sx[r][c] = x[(base + r) * C + c];
    __syncthreads();

    float bias = b_h[c];
    float acc[ROWS];
    #pragma unroll
    for (int r = 0; r < ROWS; r++) acc[r] = bias;
    for (int rr = 0; rr < C; rr++) {
        float wv = w_h[rr * C + c];
        #pragma unroll
        for (int r = 0; r < ROWS; r++) acc[r] = fmaf(sx[r][rr], wv, acc[r]);
    }
    #pragma unroll
    for (int r = 0; r < ROWS; r++) g_h[(base + r) * C + c] = acc[r];

    if (c < ROWS * 3) {
        int r = c / 3, d = c % 3;
        float a = 0.f;
        for (int rr = 0; rr < C; rr++) a = fmaf(sx[r][rr], w_s[rr * 3 + d], a);
        ss[r][d] = a;
    }
    __syncthreads();
    if (c < ROWS) {
        float a = ss[c][0], b = ss[c][1], d = ss[c][2];
        g_s4[base + c] = make_float4(a, b, d, a * a + b * b + d * d);
    }
    if (c == 0) {
        float mn = ss[0][0], mx = ss[0][0];
        #pragma unroll
        for (int r = 1; r < ROWS; r++) { mn = fminf(mn, ss[r][0]); mx = fmaxf(mx, ss[r][0]); }
        atomicMin(&g_mm[0], fenc(mn));
        atomicMax(&g_mm[1], fenc(mx));
    }
}

// ---------------- sort pipeline --------------------------------------------
__device__ __forceinline__ int bucket_of(float cx, float cmin, float scale) {
    int b = (int)((cx - cmin) * scale);
    return b < 0 ? 0 : (b > NB - 1 ? NB - 1 : b);
}

__global__ void k_hist() {
    int i = blockIdx.x * 1024 + threadIdx.x;
    float cmin = fdec(g_mm[0]);
    float scale = (float)NB / (fdec(g_mm[1]) - cmin + 1e-12f);
    atomicAdd(&g_hist[bucket_of(g_s4[i].x, cmin, scale)], 1);
}

__global__ void k_scan() {
    __shared__ int sc[NB];
    int t = threadIdx.x;             // 1024 threads, 1 block
    sc[t] = g_hist[t];
    __syncthreads();
    #pragma unroll
    for (int off = 1; off < NB; off <<= 1) {
        int v = (t >= off) ? sc[t - off] : 0;
        __syncthreads();
        sc[t] += v;
        __syncthreads();
    }
    g_base[t] = sc[t] - g_hist[t];   // exclusive
}

__global__ void k_scatter() {
    int i = blockIdx.x * 1024 + threadIdx.x;
    float4 v = g_s4[i];
    float cmin = fdec(g_mm[0]);
    float scale = (float)NB / (fdec(g_mm[1]) - cmin + 1e-12f);
    int b = bucket_of(v.x, cmin, scale);
    int pos = g_base[b] + atomicAdd(&g_cursor[b], 1);
    g_ss[pos] = v;
    g_perm[pos] = i;
}

__global__ void k_bounds() {
    __shared__ float smn[32], smx[32];
    int lane = threadIdx.x & 31;
    int wid = threadIdx.x >> 5;          // 32 warps
    int ch = blockIdx.x * 32 + wid;      // 16 blocks x 32 warps = 512 chunks
    float v = g_ss[ch * 32 + lane].x;
    float mn = v, mx = v;
    #pragma unroll
    for (int o = 16; o; o >>= 1) {
        mn = fminf(mn, __shfl_xor_sync(0xffffffffu, mn, o));
        mx = fmaxf(mx, __shfl_xor_sync(0xffffffffu, mx, o));
    }
    if (lane == 0) { g_cb[ch] = make_float2(mn, mx); smn[wid] = mn; smx[wid] = mx; }
    __syncthreads();
    if (threadIdx.x < 4) {               // 4 superchunks per block
        float a = 3.4e38f, b = -3.4e38f;
        #pragma unroll
        for (int j = 0; j < 8; j++) {
            a = fminf(a, smn[threadIdx.x * 8 + j]);
            b = fmaxf(b, smx[threadIdx.x * 8 + j]);
        }
        g_scb[blockIdx.x * 4 + threadIdx.x] = make_float2(a, b);
    }
}

// ---------------- K2: exact windowed-tau + pruned-collect kNN --------------
// Correctness guarantee: collection is always a superset of the reference
// top-40 (e<=tau with padded tau); queries whose collection would overflow CAP
// are redone exactly via a warp top-64 slot method (exact global 40th).
__global__ void __launch_bounds__(256) k2_knn() {
    __shared__ __align__(16) char sbuf[32 * CAP * 8];          // 49152 B
    float4* swin = (float4*)sbuf;                              // sweep A window
    float (*skey)[CAP] = (float(*)[CAP])sbuf;                  // rank keys
    int   (*sidx)[CAP] = (int(*)[CAP])(sbuf + 32 * CAP * 4);   // indices
    const unsigned FULL = 0xffffffffu;
    const float INF = 3.4e38f;
    int lane = threadIdx.x & 31;
    int wrp  = threadIdx.x >> 5;       // 8 warps
    int qpos0 = blockIdx.x * 32 + wrp * QPW;

    float qx[QPW], qy[QPW], qz[QPW], qw[QPW];
    int qg[QPW];
    #pragma unroll
    for (int q = 0; q < QPW; q++) {
        float4 qq = g_ss[qpos0 + q];
        qx[q] = qq.x; qy[q] = qq.y; qz[q] = qq.z; qw[q] = qq.w;
        qg[q] = g_perm[qpos0 + q];
    }

    // ---- load tau window (w halved for e-form) ----
    int ws = blockIdx.x * 32 + 16 - WIN / 2;
    if (ws < 0) ws = 0;
    if (ws > NN - WIN) ws = NN - WIN;
    for (int j = threadIdx.x; j < WIN; j += 256) {
        float4 v = g_ss[ws + j];
        v.w *= 0.5f;
        swin[j] = v;
    }
    __syncthreads();

    // ---- sweep A over window: lane-private branchless top-3 of e ----
    float t0[QPW], t1[QPW], t2[QPW];
    #pragma unroll
    for (int q = 0; q < QPW; q++) { t0[q] = INF; t1[q] = INF; t2[q] = INF; }
    #pragma unroll 2
    for (int jb = 0; jb < WIN / 32; jb++) {
        float4 cp = swin[jb * 32 + lane];
        #pragma unroll
        for (int q = 0; q < QPW; q++) {
            float e = fmaf(-qx[q], cp.x,
                      fmaf(-qy[q], cp.y,
                      fmaf(-qz[q], cp.z, cp.w)));
            float h0 = fmaxf(e, t0[q]);  t0[q] = fminf(e, t0[q]);
            float h1 = fmaxf(h0, t1[q]); t1[q] = fminf(h0, t1[q]);
            t2[q] = fminf(t2[q], h1);
        }
    }

    // ---- tau[q] = 40th smallest of kept 96 e-values, padded ----
    float tau[QPW], R2[QPW];
    #pragma unroll 1
    for (int q = 0; q < QPW; q++) {
        float h0 = t0[q], h1 = t1[q], h2 = t2[q];
        float m = INF;
        #pragma unroll 1
        for (int r = 0; r < KNN; r++) {
            m = h0;
            #pragma unroll
            for (int o = 16; o; o >>= 1) m = fminf(m, __shfl_xor_sync(FULL, m, o));
            unsigned bb = __ballot_sync(FULL, h0 == m);
            if (lane == __ffs(bb) - 1) { h0 = h1; h1 = h2; h2 = INF; }
        }
        tau[q] = m + (fabsf(m) + 0.5f * qw[q] + 2.0f) * 1e-5f;
        // d2-space prune radius (conservative): d2 <= 2*tau + qw  (+ margin)
        R2[q] = fmaf(2.0f, tau[q], qw[q]) + 1e-4f * (qw[q] + 1.0f);
    }
    float R2m = R2[0];
    float qlo = qx[0], qhi = qx[0];
    #pragma unroll
    for (int q = 1; q < QPW; q++) {
        R2m = fmaxf(R2m, R2[q]);
        qlo = fminf(qlo, qx[q]); qhi = fmaxf(qhi, qx[q]);
    }
    __syncthreads();   // swin dead; sbuf becomes skey/sidx

    // ---- sweep B: pruned collect of all candidates with e <= tau ----
    int cnt[QPW];
    #pragma unroll
    for (int q = 0; q < QPW; q++) cnt[q] = 0;
    unsigned ltmask = (1u << lane) - 1u;

    for (int sc = 0; sc < NSC; sc++) {
        float2 sb = g_scb[sc];
        float sg = fmaxf(fmaxf(sb.x - qhi, qlo - sb.y), 0.f);
        if (sg * sg > R2m) continue;
        #pragma unroll 1
        for (int ch = sc * 8; ch < sc * 8 + 8; ch++) {
            float2 cb = g_cb[ch];
            float cg = fmaxf(fmaxf(cb.x - qhi, qlo - cb.y), 0.f);
            if (cg * cg > R2m) continue;
            float4 cp = g_ss[ch * 32 + lane];
            float cw2 = 0.5f * cp.w;
            int ci = ch * 32 + lane;
            bool hitv[QPW];
            bool anyhit = false;
            #pragma unroll
            for (int q = 0; q < QPW; q++) {
                float e = fmaf(-qx[q], cp.x,
                          fmaf(-qy[q], cp.y,
                          fmaf(-qz[q], cp.z, cw2)));
                hitv[q] = (e <= tau[q]);
                anyhit = anyhit || hitv[q];
            }
            if (__ballot_sync(FULL, anyhit)) {
                #pragma unroll
                for (int q = 0; q < QPW; q++) {
                    unsigned mm = __ballot_sync(FULL, hitv[q]);
                    if (mm) {
                        int pos = cnt[q] + __popc(mm & ltmask);
                        if (hitv[q] && pos < CAP) sidx[wrp * QPW + q][pos] = ci;
                        cnt[q] += __popc(mm);
                    }
                }
            }
        }
    }
    __syncwarp();

    // ---- exact fallback for queries whose collection overflowed ----
    // cnt[] is warp-uniform. Redo with exact global 40th (top-64 slot method
    // over pruned chunks; the pruned region provably contains the true top-40
    // since R2 derives from the loose tau), then recollect with the tight tau.
    #pragma unroll 1
    for (int q = 0; q < QPW; q++) {
        if (cnt[q] <= CAP) continue;
        float d0 = INF, d1 = INF, cm = INF;
        #pragma unroll 1
        for (int ch = 0; ch < NCH; ch++) {
            float2 cb = g_cb[ch];
            float cg = fmaxf(fmaxf(cb.x - qx[q], qx[q] - cb.y), 0.f);
            if (cg * cg > R2[q]) continue;
            float4 cp = g_ss[ch * 32 + lane];
            float e = fmaf(-qx[q], cp.x,
                      fmaf(-qy[q], cp.y,
                      fmaf(-qz[q], cp.z, 0.5f * cp.w)));
            unsigned m = __ballot_sync(FULL, e < cm);
            while (m) {
                int src = __ffs(m) - 1; m &= m - 1;
                float en = __shfl_sync(FULL, e, src);
                if (en < cm) {
                    bool own = (fmaxf(d0, d1) == cm);
                    unsigned bb = __ballot_sync(FULL, own);
                    if (lane == __ffs(bb) - 1) {
                        if (d0 >= d1) d0 = en; else d1 = en;
                    }
                    float lm = fmaxf(d0, d1);
                    #pragma unroll
                    for (int o = 16; o; o >>= 1)
                        lm = fmaxf(lm, __shfl_xor_sync(FULL, lm, o));
                    cm = lm;
                }
            }
        }
        // exact 40th smallest e. FIX: slots are unsorted (replace-max fill);
        // the pop-min scan requires each lane's pair sorted ascending.
        float h0 = fminf(d0, d1), h1 = fmaxf(d0, d1), m40 = INF;
        #pragma unroll 1
        for (int r = 0; r < KNN; r++) {
            m40 = h0;
            #pragma unroll
            for (int o = 16; o; o >>= 1) m40 = fminf(m40, __shfl_xor_sync(FULL, m40, o));
            unsigned bb = __ballot_sync(FULL, h0 == m40);
            if (lane == __ffs(bb) - 1) { h0 = h1; h1 = INF; }
        }
        tau[q] = m40 + (fabsf(m40) + 0.5f * qw[q] + 2.0f) * 1e-5f;
        // recollect this query with tight tau (collection now ~45 << CAP)
        cnt[q] = 0;
        #pragma unroll 1
        for (int ch = 0; ch < NCH; ch++) {
            float2 cb = g_cb[ch];
            float cg = fmaxf(fmaxf(cb.x - qx[q], qx[q] - cb.y), 0.f);
            if (cg * cg > R2[q]) continue;
            float4 cp = g_ss[ch * 32 + lane];
            float e = fmaf(-qx[q], cp.x,
                      fmaf(-qy[q], cp.y,
                      fmaf(-qz[q], cp.z, 0.5f * cp.w)));
            bool hit = (e <= tau[q]);
            unsigned mm = __ballot_sync(FULL, hit);
            if (mm) {
                int pos = cnt[q] + __popc(mm & ltmask);
                if (hit && pos < CAP) sidx[wrp * QPW + q][pos] = ch * 32 + lane;
                cnt[q] += __popc(mm);
            }
        }
    }
    __syncwarp();

    // ---- final: exact reference-form d2, rank by (d2, orig idx), emit -----
    #pragma unroll 1
    for (int q = 0; q < QPW; q++) {
        int n = cnt[q] < CAP ? cnt[q] : CAP;
        int qs = wrp * QPW + q;
        for (int p = lane; p < n; p += 32) {
            int ci = sidx[qs][p];
            float4 cp = g_ss[ci];
            float dot = fmaf(qx[q], cp.x, fmaf(qy[q], cp.y, qz[q] * cp.z));
            skey[qs][p] = fmaf(-2.0f, dot, qw[q] + cp.w);   // reference form
            sidx[qs][p] = g_perm[ci];                        // original index
        }
        __syncwarp();
        #pragma unroll 1
        for (int base = 0; base < n; base += 32) {
            int p = base + lane;
            if (p < n) {
                float d = skey[qs][p];
                int  id = sidx[qs][p];
                int rank = 0;
                for (int e = 0; e < n; e++) {
                    float de = skey[qs][e];
                    int   ie = sidx[qs][e];
                    rank += (de < d) || (de == d && ie < id);
                }
                if (rank < KNN) {
                    float4 cp = g_s4[id];
                    float dx = qx[q] - cp.x, dy = qy[q] - cp.y, dz = qz[q] - cp.z;
                    g_idx[qg[q] * KNN + rank] = id;
                    g_ew[qg[q] * KNN + rank]  = expf(-(dx * dx + dy * dy + dz * dz + 1e-6f));
                }
            }
        }
        __syncwarp();
    }
}

// ---------------- K3: aggregate + lin + residual; BN2 partials -------------
__global__ void __launch_bounds__(256) k3_agg(const float* __restrict__ x,
                                              const float* __restrict__ w_lin,
                                              const float* __restrict__ b_lin) {
    __shared__ float  swl[3 * C * C];      // 48KB
    __shared__ float4 shs4[4][3 * C];      // 12KB
    __shared__ float  sred[2][256];
    int tid = threadIdx.x;
    int g = tid >> 6, c = tid & 63;

    for (int i = tid; i < 3 * C * C; i += 256) swl[i] = w_lin[i];
    float blc = b_lin[c];
    float psum = 0.f, psq = 0.f;

    for (int ii = blockIdx.x * 16; ii < NN; ii += PART * 16) {
        float mv[4], mxv[4], xr[4];
        #pragma unroll
        for (int b = 0; b < 4; b++) {
            int i = ii + g * 4 + b;
            const int*   ip = &g_idx[i * KNN];
            const float* wp = &g_ew[i * KNN];
            float m = 0.f, mx = -3.4e38f;
            #pragma unroll 8
            for (int k = 0; k < KNN; k++) {
                float msg = wp[k] * g_h[ip[k] * C + c];
                m += msg;
                mx = fmaxf(mx, msg);
            }
            mv[b] = m * (1.0f / KNN); mxv[b] = mx;
            xr[b] = x[i * C + c];
        }
        #pragma unroll
        for (int b = 0; b < 4; b++) {
            ((float*)&shs4[g][c])[b]         = mv[b];
            ((float*)&shs4[g][C + c])[b]     = mxv[b];
            ((float*)&shs4[g][2 * C + c])[b] = xr[b];
        }
        __syncthreads();
        float a0 = 0.f, a1 = 0.f, a2 = 0.f, a3 = 0.f;
        #pragma unroll 4
        for (int r = 0; r < 3 * C; r++) {
            float4 v = shs4[g][r];
            float w = swl[r * C + c];
            a0 = fmaf(v.x, w, a0); a1 = fmaf(v.y, w, a1);
            a2 = fmaf(v.z, w, a2); a3 = fmaf(v.w, w, a3);
        }
        float tv0 = a0 + blc + xr[0], tv1 = a1 + blc + xr[1];
        float tv2 = a2 + blc + xr[2], tv3 = a3 + blc + xr[3];
        int i0 = ii + g * 4;
        g_t[(i0 + 0) * C + c] = tv0; g_t[(i0 + 1) * C + c] = tv1;
        g_t[(i0 + 2) * C + c] = tv2; g_t[(i0 + 3) * C + c] = tv3;
        psum += (tv0 + tv1) + (tv2 + tv3);
        psq  += (tv0 * tv0 + tv1 * tv1) + (tv2 * tv2 + tv3 * tv3);
        __syncthreads();
    }
    sred[0][tid] = psum; sred[1][tid] = psq;
    __syncthreads();
    if (tid < 64) {
        float s  = sred[0][tid] + sred[0][tid + 64] + sred[0][tid + 128] + sred[0][tid + 192];
        float sq = sred[1][tid] + sred[1][tid + 64] + sred[1][tid + 128] + sred[1][tid + 192];
        g_part[0][0][tid * PART + blockIdx.x] = s;
        g_part[0][1][tid * PART + blockIdx.x] = sq;
    }
}

// ---------------- finalize BN stats (16 blocks, coalesced) -----------------
__global__ void kfin_stats(int stage) {
    __shared__ float red[2][256];
    int t = threadIdx.x;                 // 256 threads
    int c = blockIdx.x * 4 + (t >> 6);   // 4 channels per block
    int g = t & 63;
    float s = 0.f, sq = 0.f;
    for (int p = g; p < PART; p += 64) {
        s  += g_part[stage][0][c * PART + p];
        sq += g_part[stage][1][c * PART + p];
    }
    red[0][t] = s; red[1][t] = sq;
    __syncthreads();
    #pragma unroll
    for (int off = 32; off >= 1; off >>= 1) {
        if (g < off) { red[0][t] += red[0][t + off]; red[1][t] += red[1][t + off]; }
        __syncthreads();
    }
    if (g == 0) {
        float mu  = red[0][t] * (1.0f / NN);
        float var = red[1][t] * (1.0f / NN) - mu * mu;
        g_bn[stage * 2 * C + c]     = mu;
        g_bn[stage * 2 * C + C + c] = rsqrtf(var + 1e-5f);
    }
}

// ---------------- K4: BN2 + MLP + residual; BN3 partials -------------------
__global__ void __launch_bounds__(256) k4_mlp(const float* __restrict__ w_p1,
                                              const float* __restrict__ b_p1,
                                              const float* __restrict__ w_p2,
                                              const float* __restrict__ b_p2,
                                              const float* __restrict__ gamma2,
                                              const float* __restrict__ beta2) {
    __shared__ float  w1s[C * C], w2s[C * C];   // 32KB
    __shared__ float4 sy4[4][C], su4[4][C];     // 4KB
    __shared__ float  sred[2][256];
    int tid = threadIdx.x;
    int g = tid >> 6, c = tid & 63;

    for (int i = tid; i < C * C; i += 256) { w1s[i] = w_p1[i]; w2s[i] = w_p2[i]; }
    float mu = g_bn[c], rs = g_bn[C + c];
    float g2 = gamma2[c], be2 = beta2[c];
    float bp1 = b_p1[c], bp2 = b_p2[c];
    float psum = 0.f, psq = 0.f;

    for (int ii = blockIdx.x * 16; ii < NN; ii += PART * 16) {
        int i0 = ii + g * 4;
        float y[4];
        #pragma unroll
        for (int b = 0; b < 4; b++) {
            float tv = g_t[(i0 + b) * C + c];
            y[b] = fmaf((tv - mu) * rs, g2, be2);
            ((float*)&sy4[g][c])[b] = y[b];
        }
        __syncthreads();
        float a0 = 0.f, a1 = 0.f, a2 = 0.f, a3 = 0.f;
        #pragma unroll 4
        for (int r = 0; r < C; r++) {
            float4 v = sy4[g][r];
            float w = w1s[r * C + c];
            a0 = fmaf(v.x, w, a0); a1 = fmaf(v.y, w, a1);
            a2 = fmaf(v.z, w, a2); a3 = fmaf(v.w, w, a3);
        }
        a0 += bp1; a1 += bp1; a2 += bp1; a3 += bp1;
        a0 = (a0 > 0.f) ? a0 : expm1f(a0);
        a1 = (a1 > 0.f) ? a1 : expm1f(a1);
        a2 = (a2 > 0.f) ? a2 : expm1f(a2);
        a3 = (a3 > 0.f) ? a3 : expm1f(a3);
        ((float*)&su4[g][c])[0] = a0; ((float*)&su4[g][c])[1] = a1;
        ((float*)&su4[g][c])[2] = a2; ((float*)&su4[g][c])[3] = a3;
        __syncthreads();
        float z0 = 0.f, z1 = 0.f, z2 = 0.f, z3 = 0.f;
        #pragma unroll 4
        for (int r = 0; r < C; r++) {
            float4 v = su4[g][r];
            float w = w2s[r * C + c];
            z0 = fmaf(v.x, w, z0); z1 = fmaf(v.y, w, z1);
            z2 = fmaf(v.z, w, z2); z3 = fmaf(v.w, w, z3);
        }
        float v0 = y[0] + z0 + bp2, v1 = y[1] + z1 + bp2;
        float v2 = y[2] + z2 + bp2, v3 = y[3] + z3 + bp2;
        g_v[(i0 + 0) * C + c] = v0; g_v[(i0 + 1) * C + c] = v1;
        g_v[(i0 + 2) * C + c] = v2; g_v[(i0 + 3) * C + c] = v3;
        psum += (v0 + v1) + (v2 + v3);
        psq  += (v0 * v0 + v1 * v1) + (v2 * v2 + v3 * v3);
        __syncthreads();
    }
    sred[0][tid] = psum; sred[1][tid] = psq;
    __syncthreads();
    if (tid < 64) {
        float s  = sred[0][tid] + sred[0][tid + 64] + sred[0][tid + 128] + sred[0][tid + 192];
        float sq = sred[1][tid] + sred[1][tid + 64] + sred[1][tid + 128] + sred[1][tid + 192];
        g_part[1][0][tid * PART + blockIdx.x] = s;
        g_part[1][1][tid * PART + blockIdx.x] = sq;
    }
}

// ---------------- K5: final BN3 --------------------------------------------
__global__ void k5_bn3(float* __restrict__ out,
                       const float* __restrict__ gamma3,
                       const float* __restrict__ beta3) {
    int i = blockIdx.x * 256 + threadIdx.x;
    int c = i & (C - 1);
    float mu = g_bn[2 * C + c], rs = g_bn[3 * C + c];
    out[i] = fmaf((g_v[i] - mu) * rs, gamma3[c], beta3[c]);
}

// ---------------- launch ----------------------------------------------------
extern "C" void kernel_launch(void* const* d_in, const int* in_sizes, int n_in,
                              void* d_out, int out_size) {
    const float* x      = (const float*)d_in[0];
    const float* w_s    = (const float*)d_in[1];
    const float* w_h    = (const float*)d_in[2];
    const float* b_h    = (const float*)d_in[3];
    const float* w_lin  = (const float*)d_in[4];
    const float* b_lin  = (const float*)d_in[5];
    const float* w_p1   = (const float*)d_in[6];
    const float* b_p1   = (const float*)d_in[7];
    const float* w_p2   = (const float*)d_in[8];
    const float* b_p2   = (const float*)d_in[9];
    const float* gamma2 = (const float*)d_in[10];
    const float* beta2  = (const float*)d_in[11];
    const float* gamma3 = (const float*)d_in[12];
    const float* beta3  = (const float*)d_in[13];
    float* out = (float*)d_out;

    k0_init<<<1, 1024>>>();
    k1_gemm_hs<<<NN / 8, C>>>(x, w_h, b_h, w_s);
    k_hist<<<NN / 1024, 1024>>>();
    k_scan<<<1, NB>>>();
    k_scatter<<<NN / 1024, 1024>>>();
    k_bounds<<<16, 1024>>>();
    k2_knn<<<NN / 32, 256>>>();
    k3_agg<<<PART, 256>>>(x, w_lin, b_lin);
    kfin_stats<<<16, 256>>>(0);
    k4_mlp<<<PART, 256>>>(w_p1, b_p1, w_p2, b_p2, gamma2, beta2);
    kfin_stats<<<16, 256>>>(1);
    k5_bn3<<<(NN * C) / 256, 256>>>(out, gamma3, beta3);
}

// round 15
// speedup vs baseline: 1.8135x; 1.8135x over previous
#include <cuda_runtime.h>
#include <math.h>

#define NN 16384
#define C 64
#define KNN 40
#define CAP 192        // collection capacity per query
#define QPW 4          // queries per warp in kNN
#define PART 512       // partial-reduction blocks for BN stats
#define NB 1024        // sort buckets
#define WIN 4096       // tau window (128 chunks of 32) — wider than kNN ball
#define NCH (NN / 32)  // 512 candidate chunks
#define NSC (NCH / 8)  // 64 superchunks
#define K2_SMEM 65536  // dynamic smem for k2 (window 64KB > skey/sidx 48KB)

// ---------------- scratch (device globals; no allocation allowed) ----------
__device__ float    g_h[NN * C];     // propagated features
__device__ float4   g_s4[NN];        // learned coords (x,y,z,|s|^2), original order
__device__ float4   g_ss[NN];        // sorted by .x
__device__ int      g_perm[NN];      // sorted pos -> original idx
__device__ int      g_hist[NB];
__device__ int      g_base[NB];
__device__ int      g_cursor[NB];
__device__ unsigned g_mm[2];         // encoded min/max of coord x
__device__ float2   g_cb[NCH];       // per-chunk x min/max
__device__ float2   g_scb[NSC];      // per-superchunk x min/max
__device__ int      g_idx[NN * KNN];
__device__ float    g_ew[NN * KNN];
__device__ float    g_t[NN * C];
__device__ float    g_v[NN * C];
__device__ float    g_part[2][2][C * PART];
__device__ float    g_bn[4 * C];

__device__ __forceinline__ unsigned fenc(float f) {
    unsigned b = __float_as_uint(f);
    return b ^ ((-(int)(b >> 31)) | 0x80000000u);
}
__device__ __forceinline__ float fdec(unsigned e) {
    unsigned m = (e & 0x80000000u) ? 0x80000000u : 0xFFFFFFFFu;
    return __uint_as_float(e ^ m);
}

// ---------------- K0: reset sort scratch -----------------------------------
__global__ void k0_init() {
    int t = threadIdx.x;             // 1024 threads, 1 block
    g_hist[t] = 0;
    g_cursor[t] = 0;
    if (t == 0) { g_mm[0] = 0xFFFFFFFFu; g_mm[1] = 0u; }
}

// ---------------- K1: h = x@w_h + b_h ; s = x@w_s ; pack s4 + minmax -------
__global__ void k1_gemm_hs(const float* __restrict__ x,
                           const float* __restrict__ w_h,
                           const float* __restrict__ b_h,
                           const float* __restrict__ w_s) {
    const int ROWS = 8;
    __shared__ float sx[ROWS][C];
    __shared__ float ss[ROWS][3];
    int base = blockIdx.x * ROWS;
    int c = threadIdx.x; // 64 threads

    #pragma unroll
    for (int r = 0; r < ROWS; r++) sx[r][c] = x[(base + r) * C + c];
    __syncthreads();

    float bias = b_h[c];
    float acc[ROWS];
    #pragma unroll
    for (int r = 0; r < ROWS; r++) acc[r] = bias;
    for (int rr = 0; rr < C; rr++) {
        float wv = w_h[rr * C + c];
        #pragma unroll
        for (int r = 0; r < ROWS; r++) acc[r] = fmaf(sx[r][rr], wv, acc[r]);
    }
    #pragma unroll
    for (int r = 0; r < ROWS; r++) g_h[(base + r) * C + c] = acc[r];

    if (c < ROWS * 3) {
        int r = c / 3, d = c % 3;
        float a = 0.f;
        for (int rr = 0; rr < C; rr++) a = fmaf(sx[r][rr], w_s[rr * 3 + d], a);
        ss[r][d] = a;
    }
    __syncthreads();
    if (c < ROWS) {
        float a = ss[c][0], b = ss[c][1], d = ss[c][2];
        g_s4[base + c] = make_float4(a, b, d, a * a + b * b + d * d);
    }
    if (c == 0) {
        float mn = ss[0][0], mx = ss[0][0];
        #pragma unroll
        for (int r = 1; r < ROWS; r++) { mn = fminf(mn, ss[r][0]); mx = fmaxf(mx, ss[r][0]); }
        atomicMin(&g_mm[0], fenc(mn));
        atomicMax(&g_mm[1], fenc(mx));
    }
}

// ---------------- sort pipeline --------------------------------------------
__device__ __forceinline__ int bucket_of(float cx, float cmin, float scale) {
    int b = (int)((cx - cmin) * scale);
    return b < 0 ? 0 : (b > NB - 1 ? NB - 1 : b);
}

__global__ void k_hist() {
    int i = blockIdx.x * 1024 + threadIdx.x;
    float cmin = fdec(g_mm[0]);
    float scale = (float)NB / (fdec(g_mm[1]) - cmin + 1e-12f);
    atomicAdd(&g_hist[bucket_of(g_s4[i].x, cmin, scale)], 1);
}

__global__ void k_scan() {
    __shared__ int sc[NB];
    int t = threadIdx.x;             // 1024 threads, 1 block
    sc[t] = g_hist[t];
    __syncthreads();
    #pragma unroll
    for (int off = 1; off < NB; off <<= 1) {
        int v = (t >= off) ? sc[t - off] : 0;
        __syncthreads();
        sc[t] += v;
        __syncthreads();
    }
    g_base[t] = sc[t] - g_hist[t];   // exclusive
}

__global__ void k_scatter() {
    int i = blockIdx.x * 1024 + threadIdx.x;
    float4 v = g_s4[i];
    float cmin = fdec(g_mm[0]);
    float scale = (float)NB / (fdec(g_mm[1]) - cmin + 1e-12f);
    int b = bucket_of(v.x, cmin, scale);
    int pos = g_base[b] + atomicAdd(&g_cursor[b], 1);
    g_ss[pos] = v;
    g_perm[pos] = i;
}

__global__ void k_bounds() {
    __shared__ float smn[32], smx[32];
    int lane = threadIdx.x & 31;
    int wid = threadIdx.x >> 5;          // 32 warps
    int ch = blockIdx.x * 32 + wid;      // 16 blocks x 32 warps = 512 chunks
    float v = g_ss[ch * 32 + lane].x;
    float mn = v, mx = v;
    #pragma unroll
    for (int o = 16; o; o >>= 1) {
        mn = fminf(mn, __shfl_xor_sync(0xffffffffu, mn, o));
        mx = fmaxf(mx, __shfl_xor_sync(0xffffffffu, mx, o));
    }
    if (lane == 0) { g_cb[ch] = make_float2(mn, mx); smn[wid] = mn; smx[wid] = mx; }
    __syncthreads();
    if (threadIdx.x < 4) {               // 4 superchunks per block
        float a = 3.4e38f, b = -3.4e38f;
        #pragma unroll
        for (int j = 0; j < 8; j++) {
            a = fminf(a, smn[threadIdx.x * 8 + j]);
            b = fmaxf(b, smx[threadIdx.x * 8 + j]);
        }
        g_scb[blockIdx.x * 4 + threadIdx.x] = make_float2(a, b);
    }
}

// ---------------- K2: exact windowed-tau + pruned-collect kNN --------------
// Window (4096 pts) is wider than the kNN ball -> tau is near-exact ->
// collections ~40-50 << CAP; the exact fallback remains as guarantee.
__global__ void __launch_bounds__(256) k2_knn() {
    extern __shared__ __align__(16) char sbuf[];               // K2_SMEM bytes
    float4* swin = (float4*)sbuf;                              // sweep A window
    float (*skey)[CAP] = (float(*)[CAP])sbuf;                  // rank keys
    int   (*sidx)[CAP] = (int(*)[CAP])(sbuf + 32 * CAP * 4);   // indices
    const unsigned FULL = 0xffffffffu;
    const float INF = 3.4e38f;
    int lane = threadIdx.x & 31;
    int wrp  = threadIdx.x >> 5;       // 8 warps
    int qpos0 = blockIdx.x * 32 + wrp * QPW;

    float qx[QPW], qy[QPW], qz[QPW], qw[QPW];
    int qg[QPW];
    #pragma unroll
    for (int q = 0; q < QPW; q++) {
        float4 qq = g_ss[qpos0 + q];
        qx[q] = qq.x; qy[q] = qq.y; qz[q] = qq.z; qw[q] = qq.w;
        qg[q] = g_perm[qpos0 + q];
    }

    // ---- load tau window (w halved for e-form) ----
    int ws = blockIdx.x * 32 + 16 - WIN / 2;
    if (ws < 0) ws = 0;
    if (ws > NN - WIN) ws = NN - WIN;
    for (int j = threadIdx.x; j < WIN; j += 256) {
        float4 v = g_ss[ws + j];
        v.w *= 0.5f;
        swin[j] = v;
    }
    __syncthreads();

    // ---- sweep A over window: lane-private branchless top-3 of e ----
    float t0[QPW], t1[QPW], t2[QPW];
    #pragma unroll
    for (int q = 0; q < QPW; q++) { t0[q] = INF; t1[q] = INF; t2[q] = INF; }
    #pragma unroll 2
    for (int jb = 0; jb < WIN / 32; jb++) {
        float4 cp = swin[jb * 32 + lane];
        #pragma unroll
        for (int q = 0; q < QPW; q++) {
            float e = fmaf(-qx[q], cp.x,
                      fmaf(-qy[q], cp.y,
                      fmaf(-qz[q], cp.z, cp.w)));
            float h0 = fmaxf(e, t0[q]);  t0[q] = fminf(e, t0[q]);
            float h1 = fmaxf(h0, t1[q]); t1[q] = fminf(h0, t1[q]);
            t2[q] = fminf(t2[q], h1);
        }
    }

    // ---- tau[q] = 40th smallest of kept 96 e-values, padded ----
    float tau[QPW], R2[QPW];
    #pragma unroll 1
    for (int q = 0; q < QPW; q++) {
        float h0 = t0[q], h1 = t1[q], h2 = t2[q];
        float m = INF;
        #pragma unroll 1
        for (int r = 0; r < KNN; r++) {
            m = h0;
            #pragma unroll
            for (int o = 16; o; o >>= 1) m = fminf(m, __shfl_xor_sync(FULL, m, o));
            unsigned bb = __ballot_sync(FULL, h0 == m);
            if (lane == __ffs(bb) - 1) { h0 = h1; h1 = h2; h2 = INF; }
        }
        tau[q] = m + (fabsf(m) + 0.5f * qw[q] + 2.0f) * 1e-5f;
        // d2-space prune radius (conservative): d2 <= 2*tau + qw  (+ margin)
        R2[q] = fmaf(2.0f, tau[q], qw[q]) + 1e-4f * (qw[q] + 1.0f);
    }
    float R2m = R2[0];
    float qlo = qx[0], qhi = qx[0];
    #pragma unroll
    for (int q = 1; q < QPW; q++) {
        R2m = fmaxf(R2m, R2[q]);
        qlo = fminf(qlo, qx[q]); qhi = fmaxf(qhi, qx[q]);
    }
    __syncthreads();   // swin dead; sbuf becomes skey/sidx

    // ---- sweep B: pruned collect of all candidates with e <= tau ----
    int cnt[QPW];
    #pragma unroll
    for (int q = 0; q < QPW; q++) cnt[q] = 0;
    unsigned ltmask = (1u << lane) - 1u;

    for (int sc = 0; sc < NSC; sc++) {
        float2 sb = g_scb[sc];
        float sg = fmaxf(fmaxf(sb.x - qhi, qlo - sb.y), 0.f);
        if (sg * sg > R2m) continue;
        #pragma unroll 1
        for (int ch = sc * 8; ch < sc * 8 + 8; ch++) {
            float2 cb = g_cb[ch];
            float cg = fmaxf(fmaxf(cb.x - qhi, qlo - cb.y), 0.f);
            if (cg * cg > R2m) continue;
            float4 cp = g_ss[ch * 32 + lane];
            float cw2 = 0.5f * cp.w;
            int ci = ch * 32 + lane;
            bool hitv[QPW];
            bool anyhit = false;
            #pragma unroll
            for (int q = 0; q < QPW; q++) {
                float e = fmaf(-qx[q], cp.x,
                          fmaf(-qy[q], cp.y,
                          fmaf(-qz[q], cp.z, cw2)));
                hitv[q] = (e <= tau[q]);
                anyhit = anyhit || hitv[q];
            }
            if (__ballot_sync(FULL, anyhit)) {
                #pragma unroll
                for (int q = 0; q < QPW; q++) {
                    unsigned mm = __ballot_sync(FULL, hitv[q]);
                    if (mm) {
                        int pos = cnt[q] + __popc(mm & ltmask);
                        if (hitv[q] && pos < CAP) sidx[wrp * QPW + q][pos] = ci;
                        cnt[q] += __popc(mm);
                    }
                }
            }
        }
    }
    __syncwarp();

    // ---- exact fallback for queries whose collection overflowed (rare) ----
    #pragma unroll 1
    for (int q = 0; q < QPW; q++) {
        if (cnt[q] <= CAP) continue;
        float d0 = INF, d1 = INF, cm = INF;
        #pragma unroll 1
        for (int ch = 0; ch < NCH; ch++) {
            float2 cb = g_cb[ch];
            float cg = fmaxf(fmaxf(cb.x - qx[q], qx[q] - cb.y), 0.f);
            if (cg * cg > R2[q]) continue;
            float4 cp = g_ss[ch * 32 + lane];
            float e = fmaf(-qx[q], cp.x,
                      fmaf(-qy[q], cp.y,
                      fmaf(-qz[q], cp.z, 0.5f * cp.w)));
            unsigned m = __ballot_sync(FULL, e < cm);
            while (m) {
                int src = __ffs(m) - 1; m &= m - 1;
                float en = __shfl_sync(FULL, e, src);
                if (en < cm) {
                    bool own = (fmaxf(d0, d1) == cm);
                    unsigned bb = __ballot_sync(FULL, own);
                    if (lane == __ffs(bb) - 1) {
                        if (d0 >= d1) d0 = en; else d1 = en;
                    }
                    float lm = fmaxf(d0, d1);
                    #pragma unroll
                    for (int o = 16; o; o >>= 1)
                        lm = fmaxf(lm, __shfl_xor_sync(FULL, lm, o));
                    cm = lm;
                }
            }
        }
        // exact 40th smallest e (pair sorted ascending before pop-min scan)
        float h0 = fminf(d0, d1), h1 = fmaxf(d0, d1), m40 = INF;
        #pragma unroll 1
        for (int r = 0; r < KNN; r++) {
            m40 = h0;
            #pragma unroll
            for (int o = 16; o; o >>= 1) m40 = fminf(m40, __shfl_xor_sync(FULL, m40, o));
            unsigned bb = __ballot_sync(FULL, h0 == m40);
            if (lane == __ffs(bb) - 1) { h0 = h1; h1 = INF; }
        }
        tau[q] = m40 + (fabsf(m40) + 0.5f * qw[q] + 2.0f) * 1e-5f;
        cnt[q] = 0;
        #pragma unroll 1
        for (int ch = 0; ch < NCH; ch++) {
            float2 cb = g_cb[ch];
            float cg = fmaxf(fmaxf(cb.x - qx[q], qx[q] - cb.y), 0.f);
            if (cg * cg > R2[q]) continue;
            float4 cp = g_ss[ch * 32 + lane];
            float e = fmaf(-qx[q], cp.x,
                      fmaf(-qy[q], cp.y,
                      fmaf(-qz[q], cp.z, 0.5f * cp.w)));
            bool hit = (e <= tau[q]);
            unsigned mm = __ballot_sync(FULL, hit);
            if (mm) {
                int pos = cnt[q] + __popc(mm & ltmask);
                if (hit && pos < CAP) sidx[wrp * QPW + q][pos] = ch * 32 + lane;
                cnt[q] += __popc(mm);
            }
        }
    }
    __syncwarp();

    // ---- final: exact reference-form d2, rank by (d2, orig idx), emit -----
    #pragma unroll 1
    for (int q = 0; q < QPW; q++) {
        int n = cnt[q] < CAP ? cnt[q] : CAP;
        int qs = wrp * QPW + q;
        for (int p = lane; p < n; p += 32) {
            int ci = sidx[qs][p];
            float4 cp = g_ss[ci];
            float dot = fmaf(qx[q], cp.x, fmaf(qy[q], cp.y, qz[q] * cp.z));
            skey[qs][p] = fmaf(-2.0f, dot, qw[q] + cp.w);   // reference form
            sidx[qs][p] = g_perm[ci];                        // original index
        }
        __syncwarp();
        #pragma unroll 1
        for (int base = 0; base < n; base += 32) {
            int p = base + lane;
            if (p < n) {
                float d = skey[qs][p];
                int  id = sidx[qs][p];
                int rank = 0;
                for (int e = 0; e < n; e++) {
                    float de = skey[qs][e];
                    int   ie = sidx[qs][e];
                    rank += (de < d) || (de == d && ie < id);
                }
                if (rank < KNN) {
                    float4 cp = g_s4[id];
                    float dx = qx[q] - cp.x, dy = qy[q] - cp.y, dz = qz[q] - cp.z;
                    g_idx[qg[q] * KNN + rank] = id;
                    g_ew[qg[q] * KNN + rank]  = expf(-(dx * dx + dy * dy + dz * dz + 1e-6f));
                }
            }
        }
        __syncwarp();
    }
}

// ---------------- K3: aggregate + lin + residual; BN2 partials -------------
__global__ void __launch_bounds__(256) k3_agg(const float* __restrict__ x,
                                              const float* __restrict__ w_lin,
                                              const float* __restrict__ b_lin) {
    __shared__ float  swl[3 * C * C];      // 48KB
    __shared__ float4 shs4[4][3 * C];      // 12KB
    __shared__ float  sred[2][256];
    int tid = threadIdx.x;
    int g = tid >> 6, c = tid & 63;

    for (int i = tid; i < 3 * C * C; i += 256) swl[i] = w_lin[i];
    float blc = b_lin[c];
    float psum = 0.f, psq = 0.f;

    for (int ii = blockIdx.x * 16; ii < NN; ii += PART * 16) {
        float mv[4], mxv[4], xr[4];
        #pragma unroll
        for (int b = 0; b < 4; b++) {
            int i = ii + g * 4 + b;
            const int*   ip = &g_idx[i * KNN];
            const float* wp = &g_ew[i * KNN];
            float m = 0.f, mx = -3.4e38f;
            #pragma unroll 8
            for (int k = 0; k < KNN; k++) {
                float msg = wp[k] * g_h[ip[k] * C + c];
                m += msg;
                mx = fmaxf(mx, msg);
            }
            mv[b] = m * (1.0f / KNN); mxv[b] = mx;
            xr[b] = x[i * C + c];
        }
        #pragma unroll
        for (int b = 0; b < 4; b++) {
            ((float*)&shs4[g][c])[b]         = mv[b];
            ((float*)&shs4[g][C + c])[b]     = mxv[b];
            ((float*)&shs4[g][2 * C + c])[b] = xr[b];
        }
        __syncthreads();
        float a0 = 0.f, a1 = 0.f, a2 = 0.f, a3 = 0.f;
        #pragma unroll 4
        for (int r = 0; r < 3 * C; r++) {
            float4 v = shs4[g][r];
            float w = swl[r * C + c];
            a0 = fmaf(v.x, w, a0); a1 = fmaf(v.y, w, a1);
            a2 = fmaf(v.z, w, a2); a3 = fmaf(v.w, w, a3);
        }
        float tv0 = a0 + blc + xr[0], tv1 = a1 + blc + xr[1];
        float tv2 = a2 + blc + xr[2], tv3 = a3 + blc + xr[3];
        int i0 = ii + g * 4;
        g_t[(i0 + 0) * C + c] = tv0; g_t[(i0 + 1) * C + c] = tv1;
        g_t[(i0 + 2) * C + c] = tv2; g_t[(i0 + 3) * C + c] = tv3;
        psum += (tv0 + tv1) + (tv2 + tv3);
        psq  += (tv0 * tv0 + tv1 * tv1) + (tv2 * tv2 + tv3 * tv3);
        __syncthreads();
    }
    sred[0][tid] = psum; sred[1][tid] = psq;
    __syncthreads();
    if (tid < 64) {
        float s  = sred[0][tid] + sred[0][tid + 64] + sred[0][tid + 128] + sred[0][tid + 192];
        float sq = sred[1][tid] + sred[1][tid + 64] + sred[1][tid + 128] + sred[1][tid + 192];
        g_part[0][0][tid * PART + blockIdx.x] = s;
        g_part[0][1][tid * PART + blockIdx.x] = sq;
    }
}

// ---------------- finalize BN stats (16 blocks, coalesced) -----------------
__global__ void kfin_stats(int stage) {
    __shared__ float red[2][256];
    int t = threadIdx.x;                 // 256 threads
    int c = blockIdx.x * 4 + (t >> 6);   // 4 channels per block
    int g = t & 63;
    float s = 0.f, sq = 0.f;
    for (int p = g; p < PART; p += 64) {
        s  += g_part[stage][0][c * PART + p];
        sq += g_part[stage][1][c * PART + p];
    }
    red[0][t] = s; red[1][t] = sq;
    __syncthreads();
    #pragma unroll
    for (int off = 32; off >= 1; off >>= 1) {
        if (g < off) { red[0][t] += red[0][t + off]; red[1][t] += red[1][t + off]; }
        __syncthreads();
    }
    if (g == 0) {
        float mu  = red[0][t] * (1.0f / NN);
        float var = red[1][t] * (1.0f / NN) - mu * mu;
        g_bn[stage * 2 * C + c]     = mu;
        g_bn[stage * 2 * C + C + c] = rsqrtf(var + 1e-5f);
    }
}

// ---------------- K4: BN2 + MLP + residual; BN3 partials -------------------
__global__ void __launch_bounds__(256) k4_mlp(const float* __restrict__ w_p1,
                                              const float* __restrict__ b_p1,
                                              const float* __restrict__ w_p2,
                                              const float* __restrict__ b_p2,
                                              const float* __restrict__ gamma2,
                                              const float* __restrict__ beta2) {
    __shared__ float  w1s[C * C], w2s[C * C];   // 32KB
    __shared__ float4 sy4[4][C], su4[4][C];     // 4KB
    __shared__ float  sred[2][256];
    int tid = threadIdx.x;
    int g = tid >> 6, c = tid & 63;

    for (int i = tid; i < C * C; i += 256) { w1s[i] = w_p1[i]; w2s[i] = w_p2[i]; }
    float mu = g_bn[c], rs = g_bn[C + c];
    float g2 = gamma2[c], be2 = beta2[c];
    float bp1 = b_p1[c], bp2 = b_p2[c];
    float psum = 0.f, psq = 0.f;

    for (int ii = blockIdx.x * 16; ii < NN; ii += PART * 16) {
        int i0 = ii + g * 4;
        float y[4];
        #pragma unroll
        for (int b = 0; b < 4; b++) {
            float tv = g_t[(i0 + b) * C + c];
            y[b] = fmaf((tv - mu) * rs, g2, be2);
            ((float*)&sy4[g][c])[b] = y[b];
        }
        __syncthreads();
        float a0 = 0.f, a1 = 0.f, a2 = 0.f, a3 = 0.f;
        #pragma unroll 4
        for (int r = 0; r < C; r++) {
            float4 v = sy4[g][r];
            float w = w1s[r * C + c];
            a0 = fmaf(v.x, w, a0); a1 = fmaf(v.y, w, a1);
            a2 = fmaf(v.z, w, a2); a3 = fmaf(v.w, w, a3);
        }
        a0 += bp1; a1 += bp1; a2 += bp1; a3 += bp1;
        a0 = (a0 > 0.f) ? a0 : expm1f(a0);
        a1 = (a1 > 0.f) ? a1 : expm1f(a1);
        a2 = (a2 > 0.f) ? a2 : expm1f(a2);
        a3 = (a3 > 0.f) ? a3 : expm1f(a3);
        ((float*)&su4[g][c])[0] = a0; ((float*)&su4[g][c])[1] = a1;
        ((float*)&su4[g][c])[2] = a2; ((float*)&su4[g][c])[3] = a3;
        __syncthreads();
        float z0 = 0.f, z1 = 0.f, z2 = 0.f, z3 = 0.f;
        #pragma unroll 4
        for (int r = 0; r < C; r++) {
            float4 v = su4[g][r];
            float w = w2s[r * C + c];
            z0 = fmaf(v.x, w, z0); z1 = fmaf(v.y, w, z1);
            z2 = fmaf(v.z, w, z2); z3 = fmaf(v.w, w, z3);
        }
        float v0 = y[0] + z0 + bp2, v1 = y[1] + z1 + bp2;
        float v2 = y[2] + z2 + bp2, v3 = y[3] + z3 + bp2;
        g_v[(i0 + 0) * C + c] = v0; g_v[(i0 + 1) * C + c] = v1;
        g_v[(i0 + 2) * C + c] = v2; g_v[(i0 + 3) * C + c] = v3;
        psum += (v0 + v1) + (v2 + v3);
        psq  += (v0 * v0 + v1 * v1) + (v2 * v2 + v3 * v3);
        __syncthreads();
    }
    sred[0][tid] = psum; sred[1][tid] = psq;
    __syncthreads();
    if (tid < 64) {
        float s  = sred[0][tid] + sred[0][tid + 64] + sred[0][tid + 128] + sred[0][tid + 192];
        float sq = sred[1][tid] + sred[1][tid + 64] + sred[1][tid + 128] + sred[1][tid + 192];
        g_part[1][0][tid * PART + blockIdx.x] = s;
        g_part[1][1][tid * PART + blockIdx.x] = sq;
    }
}

// ---------------- K5: final BN3 --------------------------------------------
__global__ void k5_bn3(float* __restrict__ out,
                       const float* __restrict__ gamma3,
                       const float* __restrict__ beta3) {
    int i = blockIdx.x * 256 + threadIdx.x;
    int c = i & (C - 1);
    float mu = g_bn[2 * C + c], rs = g_bn[3 * C + c];
    out[i] = fmaf((g_v[i] - mu) * rs, gamma3[c], beta3[c]);
}

// ---------------- launch ----------------------------------------------------
extern "C" void kernel_launch(void* const* d_in, const int* in_sizes, int n_in,
                              void* d_out, int out_size) {
    const float* x      = (const float*)d_in[0];
    const float* w_s    = (const float*)d_in[1];
    const float* w_h    = (const float*)d_in[2];
    const float* b_h    = (const float*)d_in[3];
    const float* w_lin  = (const float*)d_in[4];
    const float* b_lin  = (const float*)d_in[5];
    const float* w_p1   = (const float*)d_in[6];
    const float* b_p1   = (const float*)d_in[7];
    const float* w_p2   = (const float*)d_in[8];
    const float* b_p2   = (const float*)d_in[9];
    const float* gamma2 = (const float*)d_in[10];
    const float* beta2  = (const float*)d_in[11];
    const float* gamma3 = (const float*)d_in[12];
    const float* beta3  = (const float*)d_in[13];
    float* out = (float*)d_out;

    static int smem_set = 0;
    if (!smem_set) {
        cudaFuncSetAttribute(k2_knn, cudaFuncAttributeMaxDynamicSharedMemorySize, K2_SMEM);
        smem_set = 1;
    }

    k0_init<<<1, 1024>>>();
    k1_gemm_hs<<<NN / 8, C>>>(x, w_h, b_h, w_s);
    k_hist<<<NN / 1024, 1024>>>();
    k_scan<<<1, NB>>>();
    k_scatter<<<NN / 1024, 1024>>>();
    k_bounds<<<16, 1024>>>();
    k2_knn<<<NN / 32, 256, K2_SMEM>>>();
    k3_agg<<<PART, 256>>>(x, w_lin, b_lin);
    kfin_stats<<<16, 256>>>(0);
    k4_mlp<<<PART, 256>>>(w_p1, b_p1, w_p2, b_p2, gamma2, beta2);
    kfin_stats<<<16, 256>>>(1);
    k5_bn3<<<(NN * C) / 256, 256>>>(out, gamma3, beta3);
}